// round 12
// baseline (speedup 1.0000x reference)
#include <cuda_runtime.h>

#define NNODES_C 10000
#define NEDGES_C 160000
typedef unsigned long long u64;

__device__ float g_nodeftr[NNODES_C * 20];   // zero at load; node_kernel re-zeroes after use
__device__ float g_tmp[NEDGES_C * 20];

static __device__ __forceinline__ u64 pack2(float x) {
    u64 r;
    asm("mov.b64 %0, {%1, %1};" : "=l"(r) : "r"(__float_as_uint(x)));
    return r;
}
static __device__ __forceinline__ float2 unpack2(u64 v) {
    float lo, hi;
    asm("mov.b64 {%0, %1}, %2;" : "=f"(lo), "=f"(hi) : "l"(v));
    return make_float2(lo, hi);
}
static __device__ __forceinline__ u64 fma2(u64 a, u64 b, u64 c) {
    u64 d;
    asm("fma.rn.f32x2 %0, %1, %2, %3;" : "=l"(d) : "l"(a), "l"(b), "l"(c));
    return d;
}
static __device__ __forceinline__ void red4(float* p, float a, float b, float c, float d) {
    asm volatile("red.global.add.v4.f32 [%0], {%1, %2, %3, %4};"
                 :: "l"(p), "f"(a), "f"(b), "f"(c), "f"(d) : "memory");
}

#define TP1_GRID 592   // 4 blocks/SM * 148 SMs, persistent
#define TP2_GRID 592

// ============================ Kernel A: MLP1 + TP1 + gating (persistent) ============================
__global__ __launch_bounds__(128, 4) void edge_tp1_kernel(
    const float* __restrict__ hn, const float* __restrict__ he,
    const int* __restrict__ esrc, const int* __restrict__ edst,
    const float* __restrict__ evec, const float* __restrict__ emb,
    const float* __restrict__ fcW1, const float* __restrict__ fcW2, int E)
{
    const float SQ3f    = 1.7320508075688772f;
    const float INVSQ3f = 0.57735026918962576f;
    const float RS10    = 0.31622776601683794f;
    const float CS1     = 0.14433756729740645f;   // 1/sqrt(48)
    const float CV1     = 0.20412414523193150f;   // 1/sqrt(24)

    __shared__ __align__(16) float sW1[160];
    __shared__ __align__(16) float sW2[9216];
    {
        const float4* g1 = (const float4*)fcW1;
        float4* d1 = (float4*)sW1;
        for (int t = threadIdx.x; t < 40; t += 128) {
            float4 a = g1[t]; d1[t] = make_float4(a.x*RS10, a.y*RS10, a.z*RS10, a.w*RS10);
        }
        const float4* g2 = (const float4*)fcW2;
        float4* d2 = (float4*)sW2;
        const float sS = CS1 * 0.25f, sV = CV1 * 0.25f;
        for (int t = threadIdx.x; t < 2304; t += 128) {
            int c0 = (t*4) % 576;
            float sc = (c0 < 288) ? sS : (c0 < 432) ? sV : (c0 < 528) ? sS : sV;
            float4 a = g2[t]; d2[t] = make_float4(a.x*sc, a.y*sc, a.z*sc, a.w*sc);
        }
    }
    __syncthreads();

    const ulonglong2* W2 = (const ulonglong2*)sW2;   // 144 chunks per k-row

    for (int e = blockIdx.x*128 + threadIdx.x; e < E; e += TP1_GRID*128) {

    // ---- gather ----
    int srcI = esrc[e], dstI = edst[e];
    float s[24], vf[36];
    {
        float4 r0[5], r1[5], r2[5];
        const float4* p = (const float4*)(he + (size_t)e*20);
#pragma unroll
        for (int i = 0; i < 5; i++) r0[i] = p[i];
        const float4* ps = (const float4*)(hn + (size_t)srcI*20);
#pragma unroll
        for (int i = 0; i < 5; i++) r1[i] = ps[i];
        const float4* pd = (const float4*)(hn + (size_t)dstI*20);
#pragma unroll
        for (int i = 0; i < 5; i++) r2[i] = pd[i];
        const float* re = (const float*)r0;
        const float* rs = (const float*)r1;
        const float* rd = (const float*)r2;
#pragma unroll
        for (int j = 0; j < 8; j++) { s[j] = re[j]; s[8+j] = rs[j]; s[16+j] = rd[j]; }
#pragma unroll
        for (int j = 0; j < 12; j++) { vf[j] = re[8+j]; vf[12+j] = rs[8+j]; vf[24+j] = rd[8+j]; }
    }

    float sh1[3];
    {
        float ex = evec[e*3+0], ey = evec[e*3+1], ez = evec[e*3+2];
        float nn = sqrtf(ex*ex + ey*ey + ez*ez) + 1e-12f;
        float f = SQ3f / nn;
        sh1[0] = ex*f; sh1[1] = ey*f; sh1[2] = ez*f;
    }
    float dots[12];
#pragma unroll
    for (int i = 0; i < 12; i++)
        dots[i] = (vf[i*3+0]*sh1[0] + vf[i*3+1]*sh1[1] + vf[i*3+2]*sh1[2]) * INVSQ3f;

    // ---- h1 = relu(emb @ fcW1/sqrt(10)) ----
    u64 h1p[16];
    {
        float embr[10];
        const float2* pe2 = (const float2*)(emb + (size_t)e*10);
#pragma unroll
        for (int j = 0; j < 5; j++) { float2 t = pe2[j]; embr[2*j] = t.x; embr[2*j+1] = t.y; }
        const ulonglong2* W = (const ulonglong2*)sW1;
        u64 acc[8];
#pragma unroll
        for (int p = 0; p < 8; p++) acc[p] = 0ull;
#pragma unroll
        for (int j = 0; j < 10; j++) {
            u64 ej = pack2(embr[j]);
#pragma unroll
            for (int g = 0; g < 4; g++) {
                ulonglong2 w = W[j*4+g];
                acc[2*g]   = fma2(ej, w.x, acc[2*g]);
                acc[2*g+1] = fma2(ej, w.y, acc[2*g+1]);
            }
        }
#pragma unroll
        for (int p = 0; p < 8; p++) {
            float2 f = unpack2(acc[p]);
            h1p[2*p]   = pack2(fmaxf(f.x, 0.f));
            h1p[2*p+1] = pack2(fmaxf(f.y, 0.f));
        }
    }

    // ---- vv: chunk 132 + i  (unrolled; consumes vf, then vf dead) ----
    u64 a1p[2][3];
#pragma unroll
    for (int c = 0; c < 3; c++) { a1p[0][c] = 0ull; a1p[1][c] = 0ull; }
#pragma unroll
    for (int i = 0; i < 12; i++) {
        u64 aA = 0ull, aB = 0ull;
#pragma unroll
        for (int k = 0; k < 16; k++) {
            ulonglong2 w = W2[k*144 + 132 + i];
            aA = fma2(h1p[k], w.x, aA);
            aB = fma2(h1p[k], w.y, aB);
        }
#pragma unroll
        for (int c = 0; c < 3; c++) {
            u64 vc2 = pack2(vf[i*3+c]);
            a1p[0][c] = fma2(vc2, aA, a1p[0][c]);
            a1p[1][c] = fma2(vc2, aB, a1p[1][c]);
        }
    }

    // shared accumulators for out0: vs accumulates first, ss adds on top
    u64 a0p[6];
#pragma unroll
    for (int p = 0; p < 6; p++) a0p[p] = 0ull;

    // ---- vs: chunk 72 + i*3 + g  (rolled; consumes dots) ----
#pragma unroll 1
    for (int i = 0; i < 12; i += 2) {
        u64 da = pack2(dots[i]);
        u64 db = pack2(dots[i+1]);
        const ulonglong2* Wb = W2 + 72 + i*3;
#pragma unroll
        for (int g = 0; g < 3; g++) {
            u64 aA = 0ull, aB = 0ull, bA = 0ull, bB = 0ull;
#pragma unroll
            for (int k = 0; k < 16; k++) {
                ulonglong2 wa = Wb[k*144 + g];
                ulonglong2 wb = Wb[k*144 + 3 + g];
                aA = fma2(h1p[k], wa.x, aA);
                aB = fma2(h1p[k], wa.y, aB);
                bA = fma2(h1p[k], wb.x, bA);
                bB = fma2(h1p[k], wb.y, bB);
            }
            a0p[2*g]   = fma2(da, aA, a0p[2*g]);
            a0p[2*g+1] = fma2(da, aB, a0p[2*g+1]);
            a0p[2*g]   = fma2(db, bA, a0p[2*g]);
            a0p[2*g+1] = fma2(db, bB, a0p[2*g+1]);
        }
    }

    // ---- ss pass A: g = 0,1 (cols 0..7), i step 2 ----
#pragma unroll 1
    for (int i = 0; i < 24; i += 2) {
        u64 sa = pack2(s[i]);
        u64 sb = pack2(s[i+1]);
        const ulonglong2* Wb = W2 + i*3;
        u64 A0=0ull, B0=0ull, A1=0ull, B1=0ull;
        u64 C0=0ull, D0=0ull, C1=0ull, D1=0ull;
#pragma unroll
        for (int k = 0; k < 16; k++) {
            ulonglong2 w0 = Wb[k*144 + 0];
            ulonglong2 w1 = Wb[k*144 + 1];
            ulonglong2 w2 = Wb[k*144 + 3];
            ulonglong2 w3 = Wb[k*144 + 4];
            A0 = fma2(h1p[k], w0.x, A0);
            B0 = fma2(h1p[k], w0.y, B0);
            A1 = fma2(h1p[k], w1.x, A1);
            B1 = fma2(h1p[k], w1.y, B1);
            C0 = fma2(h1p[k], w2.x, C0);
            D0 = fma2(h1p[k], w2.y, D0);
            C1 = fma2(h1p[k], w3.x, C1);
            D1 = fma2(h1p[k], w3.y, D1);
        }
        a0p[0] = fma2(sa, A0, a0p[0]);
        a0p[1] = fma2(sa, B0, a0p[1]);
        a0p[2] = fma2(sa, A1, a0p[2]);
        a0p[3] = fma2(sa, B1, a0p[3]);
        a0p[0] = fma2(sb, C0, a0p[0]);
        a0p[1] = fma2(sb, D0, a0p[1]);
        a0p[2] = fma2(sb, C1, a0p[2]);
        a0p[3] = fma2(sb, D1, a0p[3]);
    }

    // ---- ss pass B (g = 2) fused with sv (chunk 108+i), i step 2 ----
    u64 asvp[2];
    asvp[0] = 0ull; asvp[1] = 0ull;
#pragma unroll 1
    for (int i = 0; i < 24; i += 2) {
        u64 sa = pack2(s[i]);
        u64 sb = pack2(s[i+1]);
        const ulonglong2* Wb = W2 + i*3;
        const ulonglong2* Wv = W2 + 108 + i;
        u64 A0=0ull, B0=0ull, C0=0ull, D0=0ull;
        u64 VA=0ull, VB=0ull, VC=0ull, VD=0ull;
#pragma unroll
        for (int k = 0; k < 16; k++) {
            ulonglong2 w0 = Wb[k*144 + 2];
            ulonglong2 w1 = Wb[k*144 + 5];
            ulonglong2 v0 = Wv[k*144];
            ulonglong2 v1 = Wv[k*144 + 1];
            A0 = fma2(h1p[k], w0.x, A0);
            B0 = fma2(h1p[k], w0.y, B0);
            C0 = fma2(h1p[k], w1.x, C0);
            D0 = fma2(h1p[k], w1.y, D0);
            VA = fma2(h1p[k], v0.x, VA);
            VB = fma2(h1p[k], v0.y, VB);
            VC = fma2(h1p[k], v1.x, VC);
            VD = fma2(h1p[k], v1.y, VD);
        }
        a0p[4] = fma2(sa, A0, a0p[4]);
        a0p[5] = fma2(sa, B0, a0p[5]);
        a0p[4] = fma2(sb, C0, a0p[4]);
        a0p[5] = fma2(sb, D0, a0p[5]);
        asvp[0] = fma2(sa, VA, asvp[0]);
        asvp[1] = fma2(sa, VB, asvp[1]);
        asvp[0] = fma2(sb, VC, asvp[0]);
        asvp[1] = fma2(sb, VD, asvp[1]);
    }

    // ---- gating -> g_tmp (scales folded into weights) ----
    float outr[20];
    {
        float a0[12], asv[4], a1[4][3];
#pragma unroll
        for (int p = 0; p < 6; p++) {
            float2 f = unpack2(a0p[p]);
            a0[2*p] = f.x; a0[2*p+1] = f.y;
        }
        {
            float2 f0 = unpack2(asvp[0]); float2 f1 = unpack2(asvp[1]);
            asv[0] = f0.x; asv[1] = f0.y; asv[2] = f1.x; asv[3] = f1.y;
        }
#pragma unroll
        for (int c = 0; c < 3; c++) {
            float2 f0 = unpack2(a1p[0][c]); float2 f1 = unpack2(a1p[1][c]);
            a1[0][c] = f0.x; a1[1][c] = f0.y; a1[2][c] = f1.x; a1[3][c] = f1.y;
        }
#pragma unroll
        for (int o = 0; o < 8; o++) outr[o] = fmaxf(a0[o], 0.f);
#pragma unroll
        for (int o = 0; o < 4; o++) {
            float gate = fmaxf(a0[8+o], 0.f);
#pragma unroll
            for (int c = 0; c < 3; c++)
                outr[8 + o*3 + c] = (asv[o]*sh1[c] + a1[o][c]) * gate;
        }
    }
    {
        float4* tp = (float4*)(g_tmp + (size_t)e*20);
        const float4* sp = (const float4*)outr;
#pragma unroll
        for (int t = 0; t < 5; t++) tp[t] = sp[t];
    }

    } // persistent edge loop
}

// ============================ Kernel B: MLP2 + TP2 + epilogue (persistent) ============================
__global__ __launch_bounds__(128, 4) void edge_tp2_kernel(
    const float* __restrict__ he,
    const int* __restrict__ edst, const float* __restrict__ evec,
    const float* __restrict__ emb, const float* __restrict__ enorm,
    const float* __restrict__ fc2W1, const float* __restrict__ fc2W2,
    float* __restrict__ out_he, int E)
{
    const float SQ3f    = 1.7320508075688772f;
    const float INVSQ3f = 0.57735026918962576f;
    const float RS10    = 0.31622776601683794f;
    const float CS2     = 0.25f;
    const float CV2     = 0.35355339059327379f;

    __shared__ __align__(16) float sW1b[160];
    __shared__ __align__(16) float sW2b[2304];
    {
        const float4* g1b = (const float4*)fc2W1;
        float4* d1b = (float4*)sW1b;
        for (int t = threadIdx.x; t < 40; t += 128) {
            float4 b = g1b[t]; d1b[t] = make_float4(b.x*RS10, b.y*RS10, b.z*RS10, b.w*RS10);
        }
        const float4* g2b = (const float4*)fc2W2;
        float4* d2b = (float4*)sW2b;
        const float sS = CS2 * 0.25f, sV = CV2 * 0.25f;
        for (int t = threadIdx.x; t < 576; t += 128) {
            int c0 = (t*4) % 144;
            float sc = (c0 < 64) ? sS : (c0 < 96) ? sV : (c0 < 128) ? sS : sV;
            float4 a = g2b[t]; d2b[t] = make_float4(a.x*sc, a.y*sc, a.z*sc, a.w*sc);
        }
    }
    __syncthreads();

    const ulonglong2* W2b = (const ulonglong2*)sW2b;  // 36 chunks per k-row

    for (int e = blockIdx.x*128 + threadIdx.x; e < E; e += TP2_GRID*128) {

    float ts[8], tv[12];
    {
        float4 r[5];
        const float4* tp = (const float4*)(g_tmp + (size_t)e*20);
#pragma unroll
        for (int i = 0; i < 5; i++) r[i] = tp[i];
        const float* f = (const float*)r;
#pragma unroll
        for (int j = 0; j < 8; j++) ts[j] = f[j];
#pragma unroll
        for (int j = 0; j < 12; j++) tv[j] = f[8+j];
    }

    float sh1[3];
    {
        float ex = evec[e*3+0], ey = evec[e*3+1], ez = evec[e*3+2];
        float nn = sqrtf(ex*ex + ey*ey + ez*ez) + 1e-12f;
        float f = SQ3f / nn;
        sh1[0] = ex*f; sh1[1] = ey*f; sh1[2] = ez*f;
    }
    float dt[4];
#pragma unroll
    for (int i = 0; i < 4; i++)
        dt[i] = (tv[i*3+0]*sh1[0] + tv[i*3+1]*sh1[1] + tv[i*3+2]*sh1[2]) * INVSQ3f;

    u64 h2p[16];
    {
        float embr[10];
        const float2* pe2 = (const float2*)(emb + (size_t)e*10);
#pragma unroll
        for (int j = 0; j < 5; j++) { float2 t = pe2[j]; embr[2*j] = t.x; embr[2*j+1] = t.y; }
        const ulonglong2* W = (const ulonglong2*)sW1b;
        u64 acc[8];
#pragma unroll
        for (int p = 0; p < 8; p++) acc[p] = 0ull;
#pragma unroll
        for (int j = 0; j < 10; j++) {
            u64 ej = pack2(embr[j]);
#pragma unroll
            for (int g = 0; g < 4; g++) {
                ulonglong2 w = W[j*4+g];
                acc[2*g]   = fma2(ej, w.x, acc[2*g]);
                acc[2*g+1] = fma2(ej, w.y, acc[2*g+1]);
            }
        }
#pragma unroll
        for (int p = 0; p < 8; p++) {
            float2 f = unpack2(acc[p]);
            h2p[2*p]   = pack2(fmaxf(f.x, 0.f));
            h2p[2*p+1] = pack2(fmaxf(f.y, 0.f));
        }
    }

    u64 b0p[4], bsvp[2], b1p[2][3];
#pragma unroll
    for (int p = 0; p < 4; p++) b0p[p] = 0ull;
    bsvp[0] = 0ull; bsvp[1] = 0ull;
#pragma unroll
    for (int c = 0; c < 3; c++) { b1p[0][c] = 0ull; b1p[1][c] = 0ull; }

    // ss: chunk i*2 + g
#pragma unroll
    for (int i = 0; i < 8; i++) {
        u64 si2 = pack2(ts[i]);
#pragma unroll
        for (int g = 0; g < 2; g++) {
            u64 aA = 0ull, aB = 0ull;
#pragma unroll
            for (int k = 0; k < 16; k++) {
                ulonglong2 w = W2b[k*36 + i*2 + g];
                aA = fma2(h2p[k], w.x, aA);
                aB = fma2(h2p[k], w.y, aB);
            }
            b0p[2*g]   = fma2(si2, aA, b0p[2*g]);
            b0p[2*g+1] = fma2(si2, aB, b0p[2*g+1]);
        }
    }
    // vs: chunk 16 + i*2 + g
#pragma unroll
    for (int i = 0; i < 4; i++) {
        u64 di2 = pack2(dt[i]);
#pragma unroll
        for (int g = 0; g < 2; g++) {
            u64 aA = 0ull, aB = 0ull;
#pragma unroll
            for (int k = 0; k < 16; k++) {
                ulonglong2 w = W2b[k*36 + 16 + i*2 + g];
                aA = fma2(h2p[k], w.x, aA);
                aB = fma2(h2p[k], w.y, aB);
            }
            b0p[2*g]   = fma2(di2, aA, b0p[2*g]);
            b0p[2*g+1] = fma2(di2, aB, b0p[2*g+1]);
        }
    }
    // sv: chunk 24 + i
#pragma unroll
    for (int i = 0; i < 8; i++) {
        u64 aA = 0ull, aB = 0ull;
#pragma unroll
        for (int k = 0; k < 16; k++) {
            ulonglong2 w = W2b[k*36 + 24 + i];
            aA = fma2(h2p[k], w.x, aA);
            aB = fma2(h2p[k], w.y, aB);
        }
        u64 si2 = pack2(ts[i]);
        bsvp[0] = fma2(si2, aA, bsvp[0]);
        bsvp[1] = fma2(si2, aB, bsvp[1]);
    }
    // vv: chunk 32 + i
#pragma unroll
    for (int i = 0; i < 4; i++) {
        u64 aA = 0ull, aB = 0ull;
#pragma unroll
        for (int k = 0; k < 16; k++) {
            ulonglong2 w = W2b[k*36 + 32 + i];
            aA = fma2(h2p[k], w.x, aA);
            aB = fma2(h2p[k], w.y, aB);
        }
#pragma unroll
        for (int c = 0; c < 3; c++) {
            u64 vc2 = pack2(tv[i*3+c]);
            b1p[0][c] = fma2(vc2, aA, b1p[0][c]);
            b1p[1][c] = fma2(vc2, aB, b1p[1][c]);
        }
    }

    float b0[8], bsv[4], b1[4][3];
#pragma unroll
    for (int p = 0; p < 4; p++) {
        float2 f = unpack2(b0p[p]);
        b0[2*p] = f.x; b0[2*p+1] = f.y;
    }
    {
        float2 f0 = unpack2(bsvp[0]); float2 f1 = unpack2(bsvp[1]);
        bsv[0] = f0.x; bsv[1] = f0.y; bsv[2] = f1.x; bsv[3] = f1.y;
    }
#pragma unroll
    for (int c = 0; c < 3; c++) {
        float2 f0 = unpack2(b1p[0][c]); float2 f1 = unpack2(b1p[1][c]);
        b1[0][c] = f0.x; b1[1][c] = f0.y; b1[2][c] = f1.x; b1[3][c] = f1.y;
    }

    float hnew[20];
    {
        float4 r[5];
        const float4* p = (const float4*)(he + (size_t)e*20);
#pragma unroll
        for (int i = 0; i < 5; i++) r[i] = p[i];
        const float* re = (const float*)r;
#pragma unroll
        for (int j = 0; j < 8; j++) hnew[j] = re[j] + b0[j];
#pragma unroll
        for (int o = 0; o < 4; o++)
#pragma unroll
            for (int c = 0; c < 3; c++)
                hnew[8 + o*3 + c] = re[8+o*3+c] + (bsv[o]*sh1[c] + b1[o][c]);
    }

    {
        float4* op = (float4*)(out_he + (size_t)e*20);
        const float4* hp = (const float4*)hnew;
#pragma unroll
        for (int t = 0; t < 5; t++) op[t] = hp[t];
    }
    int dstI = edst[e];
    float nw = enorm[e];
    float* nf = &g_nodeftr[(size_t)dstI*20];
#pragma unroll
    for (int t = 0; t < 5; t++)
        red4(nf + t*4, hnew[t*4]*nw, hnew[t*4+1]*nw, hnew[t*4+2]*nw, hnew[t*4+3]*nw);

    } // persistent edge loop
}

// ============================ node kernel (also re-zeroes g_nodeftr) ============================
__global__ __launch_bounds__(32) void node_kernel(
    const float* __restrict__ hn,
    const float* __restrict__ WgS, const float* __restrict__ WgV,
    const float* __restrict__ WoS, const float* __restrict__ WoV,
    float* __restrict__ out_hn, int N)
{
    const float RS8 = 0.35355339059327379f;
    int n = blockIdx.x*32 + threadIdx.x;
    if (n >= N) return;

    float cs[16], cv[8][3];
    const float* ph = hn + (size_t)n*20;
    float* pf = g_nodeftr + (size_t)n*20;
#pragma unroll
    for (int j = 0; j < 8; j++) { cs[j] = ph[j]; cs[8+j] = pf[j]; }
#pragma unroll
    for (int i = 0; i < 4; i++)
#pragma unroll
        for (int c = 0; c < 3; c++) { cv[i][c] = ph[8+i*3+c]; cv[4+i][c] = pf[8+i*3+c]; }

    {
        float4 z4 = make_float4(0.f, 0.f, 0.f, 0.f);
        float4* pz = (float4*)pf;
#pragma unroll
        for (int t = 0; t < 5; t++) pz[t] = z4;
    }

    float gl[12];
#pragma unroll
    for (int o = 0; o < 12; o++) {
        float a = 0.f;
#pragma unroll
        for (int i = 0; i < 16; i++) a = fmaf(cs[i], __ldg(&WgS[i*12+o]), a);
        gl[o] = a * 0.25f;
    }
    float vl[4][3];
#pragma unroll
    for (int o = 0; o < 4; o++)
#pragma unroll
        for (int c = 0; c < 3; c++) {
            float a = 0.f;
#pragma unroll
            for (int i = 0; i < 8; i++) a = fmaf(cv[i][c], __ldg(&WgV[i*4+o]), a);
            vl[o][c] = a * RS8;
        }

    float ls[8], lg[4];
#pragma unroll
    for (int j = 0; j < 8; j++) ls[j] = fmaxf(gl[j], 0.f);
#pragma unroll
    for (int o = 0; o < 4; o++) lg[o] = fmaxf(gl[8+o], 0.f);

    float lv[4][3];
#pragma unroll
    for (int o = 0; o < 4; o++)
#pragma unroll
        for (int c = 0; c < 3; c++) lv[o][c] = vl[o][c] * lg[o];

    float os_[8];
#pragma unroll
    for (int o = 0; o < 8; o++) {
        float a = 0.f;
#pragma unroll
        for (int i = 0; i < 8; i++) a = fmaf(ls[i], __ldg(&WoS[i*8+o]), a);
        os_[o] = a * RS8;
    }
    float ov[4][3];
#pragma unroll
    for (int o = 0; o < 4; o++)
#pragma unroll
        for (int c = 0; c < 3; c++) {
            float a = 0.f;
#pragma unroll
            for (int i = 0; i < 4; i++) a = fmaf(lv[i][c], __ldg(&WoV[i*4+o]), a);
            ov[o][c] = a * 0.5f;
        }

    float* po = out_hn + (size_t)n*20;
#pragma unroll
    for (int j = 0; j < 8; j++) po[j] = ph[j] + os_[j];
#pragma unroll
    for (int o = 0; o < 4; o++)
#pragma unroll
        for (int c = 0; c < 3; c++) po[8+o*3+c] = ph[8+o*3+c] + ov[o][c];
}

extern "C" void kernel_launch(void* const* d_in, const int* in_sizes, int n_in,
                              void* d_out, int out_size) {
    const float* hn    = (const float*)d_in[0];
    const float* he    = (const float*)d_in[1];
    const int*   esrc  = (const int*)d_in[2];
    const int*   edst  = (const int*)d_in[3];
    const float* evec  = (const float*)d_in[4];
    const float* emb   = (const float*)d_in[5];
    const float* enorm = (const float*)d_in[6];
    const float* fcW1  = (const float*)d_in[8];
    const float* fcW2  = (const float*)d_in[9];
    const float* fc2W1 = (const float*)d_in[10];
    const float* fc2W2 = (const float*)d_in[11];
    const float* WgS   = (const float*)d_in[12];
    const float* WgV   = (const float*)d_in[13];
    const float* WoS   = (const float*)d_in[14];
    const float* WoV   = (const float*)d_in[15];

    int N = in_sizes[0] / 20;
    int E = in_sizes[1] / 20;

    float* out    = (float*)d_out;
    float* out_hn = out;                      // (N,20) first
    float* out_he = out + (size_t)N * 20;     // (E,20) second

    int g1 = (E + 127)/128; if (g1 > TP1_GRID) g1 = TP1_GRID;
    int g2 = (E + 127)/128; if (g2 > TP2_GRID) g2 = TP2_GRID;

    edge_tp1_kernel<<<g1, 128>>>(hn, he, esrc, edst, evec, emb, fcW1, fcW2, E);
    edge_tp2_kernel<<<g2, 128>>>(he, edst, evec, emb, enorm, fc2W1, fc2W2, out_he, E);
    node_kernel<<<(N + 31)/32, 32>>>(hn, WgS, WgV, WoS, WoV, out_hn, N);
}

// round 13
// speedup vs baseline: 2.0254x; 2.0254x over previous
#include <cuda_runtime.h>

#define NNODES_C 10000
#define NEDGES_C 160000
typedef unsigned long long u64;

__device__ float g_nodeftr[NNODES_C * 20];   // zero at load; node_kernel re-zeroes after use
__device__ float g_tmp[NEDGES_C * 20];

static __device__ __forceinline__ u64 pack2(float x) {
    u64 r;
    asm("mov.b64 %0, {%1, %1};" : "=l"(r) : "r"(__float_as_uint(x)));
    return r;
}
static __device__ __forceinline__ float2 unpack2(u64 v) {
    float lo, hi;
    asm("mov.b64 {%0, %1}, %2;" : "=f"(lo), "=f"(hi) : "l"(v));
    return make_float2(lo, hi);
}
static __device__ __forceinline__ u64 fma2(u64 a, u64 b, u64 c) {
    u64 d;
    asm("fma.rn.f32x2 %0, %1, %2, %3;" : "=l"(d) : "l"(a), "l"(b), "l"(c));
    return d;
}
static __device__ __forceinline__ void red4(float* p, float a, float b, float c, float d) {
    asm volatile("red.global.add.v4.f32 [%0], {%1, %2, %3, %4};"
                 :: "l"(p), "f"(a), "f"(b), "f"(c), "f"(d) : "memory");
}

// tp1 smem (floats): [0,160) W1 | [160,9376) W2 | scratch 160*25
#define TP1_THREADS 160
#define TP1_SMEM_FLOATS (160 + 9216 + TP1_THREADS*25)
#define SCR1 25

// ============================ Kernel A: MLP1 + TP1 + gating ============================
__global__ __launch_bounds__(TP1_THREADS, 4) void edge_tp1_kernel(
    const float* __restrict__ hn, const float* __restrict__ he,
    const int* __restrict__ esrc, const int* __restrict__ edst,
    const float* __restrict__ evec, const float* __restrict__ emb,
    const float* __restrict__ fcW1, const float* __restrict__ fcW2, int E)
{
    const float SQ3f    = 1.7320508075688772f;
    const float INVSQ3f = 0.57735026918962576f;
    const float RS10    = 0.31622776601683794f;
    const float CS1     = 0.14433756729740645f;   // 1/sqrt(48)
    const float CV1     = 0.20412414523193150f;   // 1/sqrt(24)

    extern __shared__ __align__(16) float smem[];
    float* sW1 = smem;
    float* sW2 = smem + 160;
    float* scr = smem + 9376;

    {
        const float4* g1 = (const float4*)fcW1;
        float4* d1 = (float4*)sW1;
        for (int t = threadIdx.x; t < 40; t += TP1_THREADS) {
            float4 a = g1[t]; d1[t] = make_float4(a.x*RS10, a.y*RS10, a.z*RS10, a.w*RS10);
        }
        const float4* g2 = (const float4*)fcW2;
        float4* d2 = (float4*)sW2;
        const float sS = CS1 * 0.25f, sV = CV1 * 0.25f;
        for (int t = threadIdx.x; t < 2304; t += TP1_THREADS) {
            int c0 = (t*4) % 576;
            float sc = (c0 < 288) ? sS : (c0 < 432) ? sV : (c0 < 528) ? sS : sV;
            float4 a = g2[t]; d2[t] = make_float4(a.x*sc, a.y*sc, a.z*sc, a.w*sc);
        }
    }
    __syncthreads();

    int e = blockIdx.x*TP1_THREADS + threadIdx.x;
    if (e >= E) return;

    float* myscr = scr + threadIdx.x * SCR1;   // s[0..24)

    // ---- gather ----
    int srcI = esrc[e], dstI = edst[e];
    float vf[36];
    {
        float4 r0[5], r1[5], r2[5];
        const float4* p = (const float4*)(he + (size_t)e*20);
#pragma unroll
        for (int i = 0; i < 5; i++) r0[i] = p[i];
        const float4* ps = (const float4*)(hn + (size_t)srcI*20);
#pragma unroll
        for (int i = 0; i < 5; i++) r1[i] = ps[i];
        const float4* pd = (const float4*)(hn + (size_t)dstI*20);
#pragma unroll
        for (int i = 0; i < 5; i++) r2[i] = pd[i];
        const float* re = (const float*)r0;
        const float* rs = (const float*)r1;
        const float* rd = (const float*)r2;
#pragma unroll
        for (int j = 0; j < 8; j++) { myscr[j] = re[j]; myscr[8+j] = rs[j]; myscr[16+j] = rd[j]; }
#pragma unroll
        for (int j = 0; j < 12; j++) { vf[j] = re[8+j]; vf[12+j] = rs[8+j]; vf[24+j] = rd[8+j]; }
    }

    float sh1[3];
    {
        float ex = evec[e*3+0], ey = evec[e*3+1], ez = evec[e*3+2];
        float nn = sqrtf(ex*ex + ey*ey + ez*ez) + 1e-12f;
        float f = SQ3f / nn;
        sh1[0] = ex*f; sh1[1] = ey*f; sh1[2] = ez*f;
    }
    float dots[12];
#pragma unroll
    for (int i = 0; i < 12; i++)
        dots[i] = (vf[i*3+0]*sh1[0] + vf[i*3+1]*sh1[1] + vf[i*3+2]*sh1[2]) * INVSQ3f;

    // ---- h1 = relu(emb @ fcW1/sqrt(10)) -> 16 floats ----
    float h1f[16];
    {
        float embr[10];
        const float2* pe2 = (const float2*)(emb + (size_t)e*10);
#pragma unroll
        for (int j = 0; j < 5; j++) { float2 t = pe2[j]; embr[2*j] = t.x; embr[2*j+1] = t.y; }
        const ulonglong2* W = (const ulonglong2*)sW1;
        u64 acc[8];
#pragma unroll
        for (int p = 0; p < 8; p++) acc[p] = 0ull;
#pragma unroll
        for (int j = 0; j < 10; j++) {
            u64 ej = pack2(embr[j]);
#pragma unroll
            for (int g = 0; g < 4; g++) {
                ulonglong2 w = W[j*4+g];
                acc[2*g]   = fma2(ej, w.x, acc[2*g]);
                acc[2*g+1] = fma2(ej, w.y, acc[2*g+1]);
            }
        }
#pragma unroll
        for (int p = 0; p < 8; p++) {
            float2 f = unpack2(acc[p]);
            h1f[2*p]   = fmaxf(f.x, 0.f);
            h1f[2*p+1] = fmaxf(f.y, 0.f);
        }
    }

    const ulonglong2* W2 = (const ulonglong2*)sW2;   // 144 chunks per k-row

    // ---- vv: chunk 132 + i  (unrolled; consumes vf, then vf dead) ----
    u64 a1p[2][3];
#pragma unroll
    for (int c = 0; c < 3; c++) { a1p[0][c] = 0ull; a1p[1][c] = 0ull; }
#pragma unroll
    for (int i = 0; i < 12; i++) {
        u64 aA = 0ull, aB = 0ull;
#pragma unroll
        for (int k = 0; k < 16; k++) {
            u64 hk = pack2(h1f[k]);
            ulonglong2 w = W2[k*144 + 132 + i];
            aA = fma2(hk, w.x, aA);
            aB = fma2(hk, w.y, aB);
        }
#pragma unroll
        for (int c = 0; c < 3; c++) {
            u64 vc2 = pack2(vf[i*3+c]);
            a1p[0][c] = fma2(vc2, aA, a1p[0][c]);
            a1p[1][c] = fma2(vc2, aB, a1p[1][c]);
        }
    }

    // shared accumulators for out0: vs accumulates first, ss adds on top
    u64 a0p[6];
#pragma unroll
    for (int p = 0; p < 6; p++) a0p[p] = 0ull;

    // ---- vs: chunk 72 + i*3 + g  (rolled; consumes dots) ----
#pragma unroll 1
    for (int i = 0; i < 12; i += 2) {
        u64 da = pack2(dots[i]);
        u64 db = pack2(dots[i+1]);
        const ulonglong2* Wb = W2 + 72 + i*3;
#pragma unroll
        for (int g = 0; g < 3; g++) {
            u64 aA = 0ull, aB = 0ull, bA = 0ull, bB = 0ull;
#pragma unroll
            for (int k = 0; k < 16; k++) {
                u64 hk = pack2(h1f[k]);
                ulonglong2 wa = Wb[k*144 + g];
                ulonglong2 wb = Wb[k*144 + 3 + g];
                aA = fma2(hk, wa.x, aA);
                aB = fma2(hk, wa.y, aB);
                bA = fma2(hk, wb.x, bA);
                bB = fma2(hk, wb.y, bB);
            }
            a0p[2*g]   = fma2(da, aA, a0p[2*g]);
            a0p[2*g+1] = fma2(da, aB, a0p[2*g+1]);
            a0p[2*g]   = fma2(db, bA, a0p[2*g]);
            a0p[2*g+1] = fma2(db, bB, a0p[2*g+1]);
        }
    }

    // ---- ss pass A: g = 0,1 (cols 0..7), i step 2 (s from scratch) ----
#pragma unroll 1
    for (int i = 0; i < 24; i += 2) {
        u64 sa = pack2(myscr[i]);
        u64 sb = pack2(myscr[i+1]);
        const ulonglong2* Wb = W2 + i*3;
        u64 A0=0ull, B0=0ull, A1=0ull, B1=0ull;
        u64 C0=0ull, D0=0ull, C1=0ull, D1=0ull;
#pragma unroll
        for (int k = 0; k < 16; k++) {
            u64 hk = pack2(h1f[k]);
            ulonglong2 w0 = Wb[k*144 + 0];
            ulonglong2 w1 = Wb[k*144 + 1];
            ulonglong2 w2 = Wb[k*144 + 3];
            ulonglong2 w3 = Wb[k*144 + 4];
            A0 = fma2(hk, w0.x, A0);
            B0 = fma2(hk, w0.y, B0);
            A1 = fma2(hk, w1.x, A1);
            B1 = fma2(hk, w1.y, B1);
            C0 = fma2(hk, w2.x, C0);
            D0 = fma2(hk, w2.y, D0);
            C1 = fma2(hk, w3.x, C1);
            D1 = fma2(hk, w3.y, D1);
        }
        a0p[0] = fma2(sa, A0, a0p[0]);
        a0p[1] = fma2(sa, B0, a0p[1]);
        a0p[2] = fma2(sa, A1, a0p[2]);
        a0p[3] = fma2(sa, B1, a0p[3]);
        a0p[0] = fma2(sb, C0, a0p[0]);
        a0p[1] = fma2(sb, D0, a0p[1]);
        a0p[2] = fma2(sb, C1, a0p[2]);
        a0p[3] = fma2(sb, D1, a0p[3]);
    }

    // ---- ss pass B (g = 2) fused with sv (chunk 108+i), i step 2 ----
    u64 asvp[2];
    asvp[0] = 0ull; asvp[1] = 0ull;
#pragma unroll 1
    for (int i = 0; i < 24; i += 2) {
        u64 sa = pack2(myscr[i]);
        u64 sb = pack2(myscr[i+1]);
        const ulonglong2* Wb = W2 + i*3;
        const ulonglong2* Wv = W2 + 108 + i;
        u64 A0=0ull, B0=0ull, C0=0ull, D0=0ull;
        u64 VA=0ull, VB=0ull, VC=0ull, VD=0ull;
#pragma unroll
        for (int k = 0; k < 16; k++) {
            u64 hk = pack2(h1f[k]);
            ulonglong2 w0 = Wb[k*144 + 2];
            ulonglong2 w1 = Wb[k*144 + 5];
            ulonglong2 v0 = Wv[k*144];
            ulonglong2 v1 = Wv[k*144 + 1];
            A0 = fma2(hk, w0.x, A0);
            B0 = fma2(hk, w0.y, B0);
            C0 = fma2(hk, w1.x, C0);
            D0 = fma2(hk, w1.y, D0);
            VA = fma2(hk, v0.x, VA);
            VB = fma2(hk, v0.y, VB);
            VC = fma2(hk, v1.x, VC);
            VD = fma2(hk, v1.y, VD);
        }
        a0p[4] = fma2(sa, A0, a0p[4]);
        a0p[5] = fma2(sa, B0, a0p[5]);
        a0p[4] = fma2(sb, C0, a0p[4]);
        a0p[5] = fma2(sb, D0, a0p[5]);
        asvp[0] = fma2(sa, VA, asvp[0]);
        asvp[1] = fma2(sa, VB, asvp[1]);
        asvp[0] = fma2(sb, VC, asvp[0]);
        asvp[1] = fma2(sb, VD, asvp[1]);
    }

    // ---- gating -> g_tmp (scales folded into weights) ----
    float outr[20];
    {
        float a0[12], asv[4], a1[4][3];
#pragma unroll
        for (int p = 0; p < 6; p++) {
            float2 f = unpack2(a0p[p]);
            a0[2*p] = f.x; a0[2*p+1] = f.y;
        }
        {
            float2 f0 = unpack2(asvp[0]); float2 f1 = unpack2(asvp[1]);
            asv[0] = f0.x; asv[1] = f0.y; asv[2] = f1.x; asv[3] = f1.y;
        }
#pragma unroll
        for (int c = 0; c < 3; c++) {
            float2 f0 = unpack2(a1p[0][c]); float2 f1 = unpack2(a1p[1][c]);
            a1[0][c] = f0.x; a1[1][c] = f0.y; a1[2][c] = f1.x; a1[3][c] = f1.y;
        }
#pragma unroll
        for (int o = 0; o < 8; o++) outr[o] = fmaxf(a0[o], 0.f);
#pragma unroll
        for (int o = 0; o < 4; o++) {
            float gate = fmaxf(a0[8+o], 0.f);
#pragma unroll
            for (int c = 0; c < 3; c++)
                outr[8 + o*3 + c] = (asv[o]*sh1[c] + a1[o][c]) * gate;
        }
    }
    {
        float4* tp = (float4*)(g_tmp + (size_t)e*20);
        const float4* sp = (const float4*)outr;
#pragma unroll
        for (int t = 0; t < 5; t++) tp[t] = sp[t];
    }
}

// ============================ Kernel B: MLP2 + TP2 + epilogue (fully unrolled) ============================
__global__ __launch_bounds__(128, 4) void edge_tp2_kernel(
    const float* __restrict__ he,
    const int* __restrict__ edst, const float* __restrict__ evec,
    const float* __restrict__ emb, const float* __restrict__ enorm,
    const float* __restrict__ fc2W1, const float* __restrict__ fc2W2,
    float* __restrict__ out_he, int E)
{
    const float SQ3f    = 1.7320508075688772f;
    const float INVSQ3f = 0.57735026918962576f;
    const float RS10    = 0.31622776601683794f;
    const float CS2     = 0.25f;
    const float CV2     = 0.35355339059327379f;

    __shared__ __align__(16) float sW1b[160];
    __shared__ __align__(16) float sW2b[2304];
    {
        const float4* g1b = (const float4*)fc2W1;
        float4* d1b = (float4*)sW1b;
        for (int t = threadIdx.x; t < 40; t += 128) {
            float4 b = g1b[t]; d1b[t] = make_float4(b.x*RS10, b.y*RS10, b.z*RS10, b.w*RS10);
        }
        const float4* g2b = (const float4*)fc2W2;
        float4* d2b = (float4*)sW2b;
        const float sS = CS2 * 0.25f, sV = CV2 * 0.25f;
        for (int t = threadIdx.x; t < 576; t += 128) {
            int c0 = (t*4) % 144;
            float sc = (c0 < 64) ? sS : (c0 < 96) ? sV : (c0 < 128) ? sS : sV;
            float4 a = g2b[t]; d2b[t] = make_float4(a.x*sc, a.y*sc, a.z*sc, a.w*sc);
        }
    }
    __syncthreads();

    int e = blockIdx.x*128 + threadIdx.x;
    if (e >= E) return;

    float ts[8], tv[12];
    {
        float4 r[5];
        const float4* tp = (const float4*)(g_tmp + (size_t)e*20);
#pragma unroll
        for (int i = 0; i < 5; i++) r[i] = tp[i];
        const float* f = (const float*)r;
#pragma unroll
        for (int j = 0; j < 8; j++) ts[j] = f[j];
#pragma unroll
        for (int j = 0; j < 12; j++) tv[j] = f[8+j];
    }

    float sh1[3];
    {
        float ex = evec[e*3+0], ey = evec[e*3+1], ez = evec[e*3+2];
        float nn = sqrtf(ex*ex + ey*ey + ez*ez) + 1e-12f;
        float f = SQ3f / nn;
        sh1[0] = ex*f; sh1[1] = ey*f; sh1[2] = ez*f;
    }
    float dt[4];
#pragma unroll
    for (int i = 0; i < 4; i++)
        dt[i] = (tv[i*3+0]*sh1[0] + tv[i*3+1]*sh1[1] + tv[i*3+2]*sh1[2]) * INVSQ3f;

    u64 h2p[16];
    {
        float embr[10];
        const float2* pe2 = (const float2*)(emb + (size_t)e*10);
#pragma unroll
        for (int j = 0; j < 5; j++) { float2 t = pe2[j]; embr[2*j] = t.x; embr[2*j+1] = t.y; }
        const ulonglong2* W = (const ulonglong2*)sW1b;
        u64 acc[8];
#pragma unroll
        for (int p = 0; p < 8; p++) acc[p] = 0ull;
#pragma unroll
        for (int j = 0; j < 10; j++) {
            u64 ej = pack2(embr[j]);
#pragma unroll
            for (int g = 0; g < 4; g++) {
                ulonglong2 w = W[j*4+g];
                acc[2*g]   = fma2(ej, w.x, acc[2*g]);
                acc[2*g+1] = fma2(ej, w.y, acc[2*g+1]);
            }
        }
#pragma unroll
        for (int p = 0; p < 8; p++) {
            float2 f = unpack2(acc[p]);
            h2p[2*p]   = pack2(fmaxf(f.x, 0.f));
            h2p[2*p+1] = pack2(fmaxf(f.y, 0.f));
        }
    }

    const ulonglong2* W2b = (const ulonglong2*)sW2b;  // 36 chunks per k-row
    u64 b0p[4], bsvp[2], b1p[2][3];
#pragma unroll
    for (int p = 0; p < 4; p++) b0p[p] = 0ull;
    bsvp[0] = 0ull; bsvp[1] = 0ull;
#pragma unroll
    for (int c = 0; c < 3; c++) { b1p[0][c] = 0ull; b1p[1][c] = 0ull; }

    // ss: chunk i*2 + g
#pragma unroll
    for (int i = 0; i < 8; i++) {
        u64 si2 = pack2(ts[i]);
#pragma unroll
        for (int g = 0; g < 2; g++) {
            u64 aA = 0ull, aB = 0ull;
#pragma unroll
            for (int k = 0; k < 16; k++) {
                ulonglong2 w = W2b[k*36 + i*2 + g];
                aA = fma2(h2p[k], w.x, aA);
                aB = fma2(h2p[k], w.y, aB);
            }
            b0p[2*g]   = fma2(si2, aA, b0p[2*g]);
            b0p[2*g+1] = fma2(si2, aB, b0p[2*g+1]);
        }
    }
    // vs: chunk 16 + i*2 + g
#pragma unroll
    for (int i = 0; i < 4; i++) {
        u64 di2 = pack2(dt[i]);
#pragma unroll
        for (int g = 0; g < 2; g++) {
            u64 aA = 0ull, aB = 0ull;
#pragma unroll
            for (int k = 0; k < 16; k++) {
                ulonglong2 w = W2b[k*36 + 16 + i*2 + g];
                aA = fma2(h2p[k], w.x, aA);
                aB = fma2(h2p[k], w.y, aB);
            }
            b0p[2*g]   = fma2(di2, aA, b0p[2*g]);
            b0p[2*g+1] = fma2(di2, aB, b0p[2*g+1]);
        }
    }
    // sv: chunk 24 + i
#pragma unroll
    for (int i = 0; i < 8; i++) {
        u64 aA = 0ull, aB = 0ull;
#pragma unroll
        for (int k = 0; k < 16; k++) {
            ulonglong2 w = W2b[k*36 + 24 + i];
            aA = fma2(h2p[k], w.x, aA);
            aB = fma2(h2p[k], w.y, aB);
        }
        u64 si2 = pack2(ts[i]);
        bsvp[0] = fma2(si2, aA, bsvp[0]);
        bsvp[1] = fma2(si2, aB, bsvp[1]);
    }
    // vv: chunk 32 + i
#pragma unroll
    for (int i = 0; i < 4; i++) {
        u64 aA = 0ull, aB = 0ull;
#pragma unroll
        for (int k = 0; k < 16; k++) {
            ulonglong2 w = W2b[k*36 + 32 + i];
            aA = fma2(h2p[k], w.x, aA);
            aB = fma2(h2p[k], w.y, aB);
        }
#pragma unroll
        for (int c = 0; c < 3; c++) {
            u64 vc2 = pack2(tv[i*3+c]);
            b1p[0][c] = fma2(vc2, aA, b1p[0][c]);
            b1p[1][c] = fma2(vc2, aB, b1p[1][c]);
        }
    }

    float b0[8], bsv[4], b1[4][3];
#pragma unroll
    for (int p = 0; p < 4; p++) {
        float2 f = unpack2(b0p[p]);
        b0[2*p] = f.x; b0[2*p+1] = f.y;
    }
    {
        float2 f0 = unpack2(bsvp[0]); float2 f1 = unpack2(bsvp[1]);
        bsv[0] = f0.x; bsv[1] = f0.y; bsv[2] = f1.x; bsv[3] = f1.y;
    }
#pragma unroll
    for (int c = 0; c < 3; c++) {
        float2 f0 = unpack2(b1p[0][c]); float2 f1 = unpack2(b1p[1][c]);
        b1[0][c] = f0.x; b1[1][c] = f0.y; b1[2][c] = f1.x; b1[3][c] = f1.y;
    }

    float hnew[20];
    {
        float4 r[5];
        const float4* p = (const float4*)(he + (size_t)e*20);
#pragma unroll
        for (int i = 0; i < 5; i++) r[i] = p[i];
        const float* re = (const float*)r;
#pragma unroll
        for (int j = 0; j < 8; j++) hnew[j] = re[j] + b0[j];
#pragma unroll
        for (int o = 0; o < 4; o++)
#pragma unroll
            for (int c = 0; c < 3; c++)
                hnew[8 + o*3 + c] = re[8+o*3+c] + (bsv[o]*sh1[c] + b1[o][c]);
    }

    {
        float4* op = (float4*)(out_he + (size_t)e*20);
        const float4* hp = (const float4*)hnew;
#pragma unroll
        for (int t = 0; t < 5; t++) op[t] = hp[t];
    }
    int dstI = edst[e];
    float nw = enorm[e];
    float* nf = &g_nodeftr[(size_t)dstI*20];
#pragma unroll
    for (int t = 0; t < 5; t++)
        red4(nf + t*4, hnew[t*4]*nw, hnew[t*4+1]*nw, hnew[t*4+2]*nw, hnew[t*4+3]*nw);
}

// ============================ node kernel (also re-zeroes g_nodeftr) ============================
__global__ __launch_bounds__(32) void node_kernel(
    const float* __restrict__ hn,
    const float* __restrict__ WgS, const float* __restrict__ WgV,
    const float* __restrict__ WoS, const float* __restrict__ WoV,
    float* __restrict__ out_hn, int N)
{
    const float RS8 = 0.35355339059327379f;
    int n = blockIdx.x*32 + threadIdx.x;
    if (n >= N) return;

    float cs[16], cv[8][3];
    const float* ph = hn + (size_t)n*20;
    float* pf = g_nodeftr + (size_t)n*20;
#pragma unroll
    for (int j = 0; j < 8; j++) { cs[j] = ph[j]; cs[8+j] = pf[j]; }
#pragma unroll
    for (int i = 0; i < 4; i++)
#pragma unroll
        for (int c = 0; c < 3; c++) { cv[i][c] = ph[8+i*3+c]; cv[4+i][c] = pf[8+i*3+c]; }

    {
        float4 z4 = make_float4(0.f, 0.f, 0.f, 0.f);
        float4* pz = (float4*)pf;
#pragma unroll
        for (int t = 0; t < 5; t++) pz[t] = z4;
    }

    float gl[12];
#pragma unroll
    for (int o = 0; o < 12; o++) {
        float a = 0.f;
#pragma unroll
        for (int i = 0; i < 16; i++) a = fmaf(cs[i], __ldg(&WgS[i*12+o]), a);
        gl[o] = a * 0.25f;
    }
    float vl[4][3];
#pragma unroll
    for (int o = 0; o < 4; o++)
#pragma unroll
        for (int c = 0; c < 3; c++) {
            float a = 0.f;
#pragma unroll
            for (int i = 0; i < 8; i++) a = fmaf(cv[i][c], __ldg(&WgV[i*4+o]), a);
            vl[o][c] = a * RS8;
        }

    float ls[8], lg[4];
#pragma unroll
    for (int j = 0; j < 8; j++) ls[j] = fmaxf(gl[j], 0.f);
#pragma unroll
    for (int o = 0; o < 4; o++) lg[o] = fmaxf(gl[8+o], 0.f);

    float lv[4][3];
#pragma unroll
    for (int o = 0; o < 4; o++)
#pragma unroll
        for (int c = 0; c < 3; c++) lv[o][c] = vl[o][c] * lg[o];

    float os_[8];
#pragma unroll
    for (int o = 0; o < 8; o++) {
        float a = 0.f;
#pragma unroll
        for (int i = 0; i < 8; i++) a = fmaf(ls[i], __ldg(&WoS[i*8+o]), a);
        os_[o] = a * RS8;
    }
    float ov[4][3];
#pragma unroll
    for (int o = 0; o < 4; o++)
#pragma unroll
        for (int c = 0; c < 3; c++) {
            float a = 0.f;
#pragma unroll
            for (int i = 0; i < 4; i++) a = fmaf(lv[i][c], __ldg(&WoV[i*4+o]), a);
            ov[o][c] = a * 0.5f;
        }

    float* po = out_hn + (size_t)n*20;
#pragma unroll
    for (int j = 0; j < 8; j++) po[j] = ph[j] + os_[j];
#pragma unroll
    for (int o = 0; o < 4; o++)
#pragma unroll
        for (int c = 0; c < 3; c++) po[8+o*3+c] = ph[8+o*3+c] + ov[o][c];
}

extern "C" void kernel_launch(void* const* d_in, const int* in_sizes, int n_in,
                              void* d_out, int out_size) {
    const float* hn    = (const float*)d_in[0];
    const float* he    = (const float*)d_in[1];
    const int*   esrc  = (const int*)d_in[2];
    const int*   edst  = (const int*)d_in[3];
    const float* evec  = (const float*)d_in[4];
    const float* emb   = (const float*)d_in[5];
    const float* enorm = (const float*)d_in[6];
    const float* fcW1  = (const float*)d_in[8];
    const float* fcW2  = (const float*)d_in[9];
    const float* fc2W1 = (const float*)d_in[10];
    const float* fc2W2 = (const float*)d_in[11];
    const float* WgS   = (const float*)d_in[12];
    const float* WgV   = (const float*)d_in[13];
    const float* WoS   = (const float*)d_in[14];
    const float* WoV   = (const float*)d_in[15];

    int N = in_sizes[0] / 20;
    int E = in_sizes[1] / 20;

    float* out    = (float*)d_out;
    float* out_hn = out;                      // (N,20) first
    float* out_he = out + (size_t)N * 20;     // (E,20) second

    size_t tp1_smem = TP1_SMEM_FLOATS * sizeof(float);
    cudaFuncSetAttribute(edge_tp1_kernel,
                         cudaFuncAttributeMaxDynamicSharedMemorySize, (int)tp1_smem);

    edge_tp1_kernel<<<(E + TP1_THREADS - 1)/TP1_THREADS, TP1_THREADS, tp1_smem>>>(
        hn, he, esrc, edst, evec, emb, fcW1, fcW2, E);
    edge_tp2_kernel<<<(E + 127)/128, 128>>>(he, edst, evec, emb, enorm, fc2W1, fc2W2, out_he, E);
    node_kernel<<<(N + 31)/32, 32>>>(hn, WgS, WgV, WoS, WoV, out_hn, N);
}